// round 11
// baseline (speedup 1.0000x reference)
#include <cuda_runtime.h>
#include <cuda_bf16.h>
#include <cuda_fp16.h>
#include <cstdint>

#define NNODES 100000
#define NEDGES 1600000
#define FIN    128
#define FHID   128
#define FOUT   40

#define SCAN_BS 1024
#define SCAN_NBLK ((NNODES + SCAN_BS - 1) / SCAN_BS)   // 98

typedef unsigned long long ull;

// ---------------- device scratch ----------------
__device__ __half2 g_h1h [(size_t)NNODES * (FHID / 2)]; // x @ W1, fp16
__device__ __half2 g_h1bh[(size_t)NNODES * (FHID / 2)]; // relu(agg1 + b1), fp16
__device__ __half2 g_h2h [(size_t)NNODES * (FOUT / 2)]; // h1b @ W2, fp16
__device__ int   g_src[NEDGES];
__device__ int   g_dst[NEDGES];
__device__ int   g_deg[NNODES];
__device__ int   g_cur[NNODES];
__device__ float g_dis[NNODES];
__device__ int   g_off[NNODES + 1];
__device__ int   g_bsum[SCAN_NBLK];
__device__ int   g_boff[SCAN_NBLK];
__device__ int2  g_srcw[NEDGES];                 // {src, bits(dis[src])} grouped by dst
__device__ int   g_is64;

// packed f32x2 fma: d = a*b + d
__device__ __forceinline__ void ffma2(ull& d, ull a, ull b) {
    asm("fma.rn.f32x2 %0, %1, %2, %3;" : "=l"(d) : "l"(a), "l"(b), "l"(d));
}
__device__ __forceinline__ float2 unpack2(ull v) {
    float2 f;
    asm("mov.b64 {%0, %1}, %2;" : "=f"(f.x), "=f"(f.y) : "l"(v));
    return f;
}

// ---------------- fused: edge-format detect (block 0) + deg/cur init --------
__global__ void k_pre(const int* __restrict__ ei) {
    int v = blockIdx.x * blockDim.x + threadIdx.x;
    if (v < NNODES) { g_deg[v] = 1; g_cur[v] = 0; }
    if (blockIdx.x == 0) {
        __shared__ int cnt;
        if (threadIdx.x == 0) cnt = 0;
        __syncthreads();
        int nz = 0;
        const int STRIDE = NEDGES / 4096;     // 390
        for (int i = threadIdx.x; i < 4096; i += 256) {
            size_t idx = (size_t)i * STRIDE * 2 + 1;
            if (ei[idx] != 0) nz++;
        }
        atomicAdd(&cnt, nz);
        __syncthreads();
        if (threadIdx.x == 0) g_is64 = (cnt == 0);
    }
}

// ---------------- repack + degree count fused ----------------
__global__ void k_repack_count(const int* __restrict__ ei) {
    int e = blockIdx.x * blockDim.x + threadIdx.x;
    if (e >= NEDGES) return;
    int s, d;
    if (g_is64) {
        s = ei[2 * e];
        d = ei[2 * NEDGES + 2 * e];
    } else {
        s = ei[e];
        d = ei[NEDGES + e];
    }
    g_src[e] = s;
    g_dst[e] = d;
    atomicAdd(&g_deg[d], 1);
}

// ---------------- parallel scan, phase 1 + dis ----------------
__global__ __launch_bounds__(SCAN_BS) void k_scan1() {
    __shared__ int sh[SCAN_BS];
    int t = threadIdx.x;
    int i = blockIdx.x * SCAN_BS + t;
    int v = 0;
    if (i < NNODES) {
        int dg = g_deg[i];
        v = dg - 1;                        // CSR holds only real edges
        g_dis[i] = rsqrtf((float)dg);      // norm uses deg incl self
    }
    sh[t] = v;
    __syncthreads();
#pragma unroll
    for (int off = 1; off < SCAN_BS; off <<= 1) {
        int add = (t >= off) ? sh[t - off] : 0;
        __syncthreads();
        sh[t] += add;
        __syncthreads();
    }
    if (i < NNODES) g_off[i] = sh[t] - v;
    if (t == SCAN_BS - 1) g_bsum[blockIdx.x] = sh[t];
}

// ---------------- parallel scan, phase 2 ----------------
__global__ void k_scan2() {
    __shared__ int sh[128];
    int t = threadIdx.x;
    int v = (t < SCAN_NBLK) ? g_bsum[t] : 0;
    sh[t] = v;
    __syncthreads();
#pragma unroll
    for (int off = 1; off < 128; off <<= 1) {
        int add = (t >= off) ? sh[t - off] : 0;
        __syncthreads();
        sh[t] += add;
        __syncthreads();
    }
    if (t < SCAN_NBLK) g_boff[t] = sh[t] - v;
}

// ---------------- parallel scan, phase 3 ----------------
__global__ __launch_bounds__(SCAN_BS) void k_scan3() {
    int i = blockIdx.x * SCAN_BS + threadIdx.x;
    if (i < NNODES) g_off[i] += g_boff[blockIdx.x];
    if (i == 0) g_off[NNODES] = NEDGES;
}

__global__ void k_scatter() {
    int e = blockIdx.x * blockDim.x + threadIdx.x;
    if (e >= NEDGES) return;
    int s = g_src[e];
    int d = g_dst[e];
    int pos = g_off[d] + atomicAdd(&g_cur[d], 1);
    g_srcw[pos] = make_int2(s, __float_as_int(g_dis[s]));
}

// ---------------- GEMM1: h1 = x @ W1 -> fp16  (f32x2 packed) ----------------
__global__ __launch_bounds__(128) void k_gemm1(const float* __restrict__ x,
                                               const float* __restrict__ W) {
    __shared__ __align__(16) float2 xsT2[128][34];
    int t = threadIdx.x;
    int row0 = blockIdx.x * 32;
#pragma unroll
    for (int i = 0; i < 32; i++) {
        float v = x[(size_t)(row0 + i) * FIN + t];
        xsT2[t][i] = make_float2(v, v);
    }
    __syncthreads();

    int tx = t & 15;
    int ty = t >> 4;
    ull acc[4][4];
#pragma unroll
    for (int r = 0; r < 4; r++)
#pragma unroll
        for (int c = 0; c < 4; c++) acc[r][c] = 0ull;

    const float* Wc = W + tx * 8;
#pragma unroll 4
    for (int k = 0; k < 128; k++) {
        const ulonglong2* ap = (const ulonglong2*)&xsT2[k][ty * 4];
        ulonglong2 A01 = ap[0];
        ulonglong2 A23 = ap[1];
        const ulonglong2* bp = (const ulonglong2*)&Wc[(size_t)k * FHID];
        ulonglong2 B03 = bp[0];
        ulonglong2 B47 = bp[1];
        ffma2(acc[0][0], A01.x, B03.x); ffma2(acc[0][1], A01.x, B03.y);
        ffma2(acc[0][2], A01.x, B47.x); ffma2(acc[0][3], A01.x, B47.y);
        ffma2(acc[1][0], A01.y, B03.x); ffma2(acc[1][1], A01.y, B03.y);
        ffma2(acc[1][2], A01.y, B47.x); ffma2(acc[1][3], A01.y, B47.y);
        ffma2(acc[2][0], A23.x, B03.x); ffma2(acc[2][1], A23.x, B03.y);
        ffma2(acc[2][2], A23.x, B47.x); ffma2(acc[2][3], A23.x, B47.y);
        ffma2(acc[3][0], A23.y, B03.x); ffma2(acc[3][1], A23.y, B03.y);
        ffma2(acc[3][2], A23.y, B47.x); ffma2(acc[3][3], A23.y, B47.y);
    }
#pragma unroll
    for (int r = 0; r < 4; r++) {
        __half2 h0 = __float22half2_rn(unpack2(acc[r][0]));
        __half2 h1 = __float22half2_rn(unpack2(acc[r][1]));
        __half2 h2 = __float22half2_rn(unpack2(acc[r][2]));
        __half2 h3 = __float22half2_rn(unpack2(acc[r][3]));
        uint4 o;
        o.x = *(uint32_t*)&h0; o.y = *(uint32_t*)&h1;
        o.z = *(uint32_t*)&h2; o.w = *(uint32_t*)&h3;
        *(uint4*)(g_h1h + (size_t)(row0 + ty * 4 + r) * (FHID / 2) + tx * 4) = o;
    }
}

// ---------------- agg1: paired-edge gather, 2 edges per warp-load -----------
// lanes 0-15 edge i, lanes 16-31 edge i+1; each lane: uint4 = 8 fp16 feats.
// self loop folded as virtual edge {w, dv} at index deg.
__global__ __launch_bounds__(256) void k_agg1(const float* __restrict__ b1) {
    int w = blockIdx.x * 8 + (threadIdx.x >> 5);
    int lane = threadIdx.x & 31;
    if (w >= NNODES) return;
    int half = lane >> 4;
    int sub  = lane & 15;
    int j0 = g_off[w];
    int deg = g_off[w + 1] - j0;
    float dv = g_dis[w];
    int n = deg + 1;                    // + virtual self edge
    const uint4* base = (const uint4*)g_h1h;   // 16 uint4 per row
    float acc[8];
#pragma unroll
    for (int c = 0; c < 8; c++) acc[c] = 0.f;

#define ACCQ(r, wt) { \
        float2 f0 = __half22float2(*(__half2*)&(r).x); \
        float2 f1 = __half22float2(*(__half2*)&(r).y); \
        float2 f2 = __half22float2(*(__half2*)&(r).z); \
        float2 f3 = __half22float2(*(__half2*)&(r).w); \
        acc[0] += (wt) * f0.x; acc[1] += (wt) * f0.y; \
        acc[2] += (wt) * f1.x; acc[3] += (wt) * f1.y; \
        acc[4] += (wt) * f2.x; acc[5] += (wt) * f2.y; \
        acc[6] += (wt) * f3.x; acc[7] += (wt) * f3.y; }

    int i = 0;
    for (; i + 4 <= n; i += 4) {       // 4 edges per iteration (2 per half)
        int ia = i + half, ib = i + 2 + half;
        int2 ea = (ia < deg) ? g_srcw[j0 + ia] : make_int2(w, __float_as_int(dv));
        int2 eb = (ib < deg) ? g_srcw[j0 + ib] : make_int2(w, __float_as_int(dv));
        uint4 ra = base[(size_t)ea.x * 16 + sub];
        uint4 rb = base[(size_t)eb.x * 16 + sub];
        float wa = __int_as_float(ea.y), wb = __int_as_float(eb.y);
        ACCQ(ra, wa) ACCQ(rb, wb)
    }
    for (; i < n; i += 2) {
        int idx = i + half;
        if (idx < n) {
            int2 e = (idx < deg) ? g_srcw[j0 + idx] : make_int2(w, __float_as_int(dv));
            uint4 r = base[(size_t)e.x * 16 + sub];
            float wt = __int_as_float(e.y);
            ACCQ(r, wt)
        }
    }
#undef ACCQ
#pragma unroll
    for (int c = 0; c < 8; c++)
        acc[c] += __shfl_down_sync(0xffffffff, acc[c], 16);

    if (half == 0) {
        const float4* bbp = (const float4*)(b1 + sub * 8);
        float4 b0 = bbp[0], b1v = bbp[1];
        float r0 = fmaxf(fmaf(dv, acc[0], b0.x), 0.f);
        float r1 = fmaxf(fmaf(dv, acc[1], b0.y), 0.f);
        float r2 = fmaxf(fmaf(dv, acc[2], b0.z), 0.f);
        float r3 = fmaxf(fmaf(dv, acc[3], b0.w), 0.f);
        float r4 = fmaxf(fmaf(dv, acc[4], b1v.x), 0.f);
        float r5 = fmaxf(fmaf(dv, acc[5], b1v.y), 0.f);
        float r6 = fmaxf(fmaf(dv, acc[6], b1v.z), 0.f);
        float r7 = fmaxf(fmaf(dv, acc[7], b1v.w), 0.f);
        __half2 h0 = __floats2half2_rn(r0, r1);
        __half2 h1 = __floats2half2_rn(r2, r3);
        __half2 h2 = __floats2half2_rn(r4, r5);
        __half2 h3 = __floats2half2_rn(r6, r7);
        uint4 o;
        o.x = *(uint32_t*)&h0; o.y = *(uint32_t*)&h1;
        o.z = *(uint32_t*)&h2; o.w = *(uint32_t*)&h3;
        *(uint4*)(g_h1bh + (size_t)w * (FHID / 2) + sub * 4) = o;
    }
}

// ---------------- GEMM2: h2 = h1b(fp16) @ W2 -> fp16 ----------------
__global__ __launch_bounds__(160) void k_gemm2(const float* __restrict__ W2) {
    __shared__ float xs[32][133];
    __shared__ __align__(16) float ws[128 * 40];
    int t = threadIdx.x;
    int row0 = blockIdx.x * 32;
    for (int i = t; i < 128 * 40; i += 160) ws[i] = W2[i];
    for (int i = t; i < 32 * 64; i += 160) {       // 64 half2 per row
        int r = i >> 6, c2 = i & 63;
        float2 f = __half22float2(g_h1bh[(size_t)(row0 + r) * 64 + c2]);
        xs[r][2 * c2]     = f.x;
        xs[r][2 * c2 + 1] = f.y;
    }
    __syncthreads();

    int row = t & 31;
    int cy = t >> 5;
    ull acc[4];
#pragma unroll
    for (int c = 0; c < 4; c++) acc[c] = 0ull;
#pragma unroll 4
    for (int k = 0; k < 128; k++) {
        float a = xs[row][k];
        ull ad;
        asm("mov.b64 %0, {%1, %1};" : "=l"(ad) : "f"(a));
        const ulonglong2* bp = (const ulonglong2*)&ws[k * 40 + cy * 8];
        ulonglong2 B03 = bp[0], B47 = bp[1];
        ffma2(acc[0], ad, B03.x); ffma2(acc[1], ad, B03.y);
        ffma2(acc[2], ad, B47.x); ffma2(acc[3], ad, B47.y);
    }
    __half2 h0 = __float22half2_rn(unpack2(acc[0]));
    __half2 h1 = __float22half2_rn(unpack2(acc[1]));
    __half2 h2 = __float22half2_rn(unpack2(acc[2]));
    __half2 h3 = __float22half2_rn(unpack2(acc[3]));
    uint4 o;
    o.x = *(uint32_t*)&h0; o.y = *(uint32_t*)&h1;
    o.z = *(uint32_t*)&h2; o.w = *(uint32_t*)&h3;
    *(uint4*)(g_h2h + (size_t)(row0 + row) * (FOUT / 2) + cy * 4) = o;
}

// ---------------- agg2: out = dv*(sum dis[s]*h2[s] + dv*h2[v]) + b2 ---------
__global__ __launch_bounds__(256) void k_agg2(const float* __restrict__ b2,
                                              float* __restrict__ out) {
    int w = blockIdx.x * 8 + (threadIdx.x >> 5);
    int lane = threadIdx.x & 31;
    if (w >= NNODES || lane >= 20) return;
    int j = g_off[w], end = g_off[w + 1];
    float2 acc = make_float2(0.f, 0.f);
    for (; j + 2 <= end; j += 2) {
        int2 e0 = g_srcw[j], e1 = g_srcw[j + 1];
        __half2 v0 = g_h2h[(size_t)e0.x * (FOUT / 2) + lane];
        __half2 v1 = g_h2h[(size_t)e1.x * (FOUT / 2) + lane];
        float w0 = __int_as_float(e0.y), w1 = __int_as_float(e1.y);
        float2 f0 = __half22float2(v0), f1 = __half22float2(v1);
        acc.x += w0 * f0.x + w1 * f1.x;
        acc.y += w0 * f0.y + w1 * f1.y;
    }
    if (j < end) {
        int2 e0 = g_srcw[j];
        __half2 v0 = g_h2h[(size_t)e0.x * (FOUT / 2) + lane];
        float w0 = __int_as_float(e0.y);
        float2 f0 = __half22float2(v0);
        acc.x += w0 * f0.x;
        acc.y += w0 * f0.y;
    }
    float dv = g_dis[w];
    {   // analytic self loop
        __half2 vs = g_h2h[(size_t)w * (FOUT / 2) + lane];
        float2 fs = __half22float2(vs);
        acc.x += dv * fs.x;
        acc.y += dv * fs.y;
    }
    float2 bb = ((const float2*)b2)[lane];
    float2 o;
    o.x = fmaf(dv, acc.x, bb.x);
    o.y = fmaf(dv, acc.y, bb.y);
    ((float2*)(out + (size_t)w * FOUT))[lane] = o;
}

// ---------------- stream/event resources (created at program load) ----------
struct SideStream {
    cudaStream_t s;
    cudaEvent_t  evFork, evJoin;
    SideStream() {
        cudaStreamCreateWithFlags(&s, cudaStreamNonBlocking);
        cudaEventCreateWithFlags(&evFork, cudaEventDisableTiming);
        cudaEventCreateWithFlags(&evJoin, cudaEventDisableTiming);
    }
};
static SideStream g_ss;

// ---------------- launcher ----------------
extern "C" void kernel_launch(void* const* d_in, const int* in_sizes, int n_in,
                              void* d_out, int out_size) {
    const float* x  = nullptr;
    const int*   ei = nullptr;
    const float* W1 = nullptr;
    const float* b1 = nullptr;
    const float* W2 = nullptr;
    const float* b2 = nullptr;
    for (int i = 0; i < n_in; i++) {
        switch (in_sizes[i]) {
            case NNODES * FIN: x  = (const float*)d_in[i]; break;
            case 2 * NEDGES:   ei = (const int*)  d_in[i]; break;
            case FIN * FHID:   W1 = (const float*)d_in[i]; break;
            case FHID:         b1 = (const float*)d_in[i]; break;
            case FHID * FOUT:  W2 = (const float*)d_in[i]; break;
            case FOUT:         b2 = (const float*)d_in[i]; break;
        }
    }
    float* out = (float*)d_out;

    // fork: CSR build chain on side stream, GEMM1 on main stream
    cudaEventRecord(g_ss.evFork, 0);
    cudaStreamWaitEvent(g_ss.s, g_ss.evFork, 0);

    k_pre          <<<(NNODES + 255) / 256, 256, 0, g_ss.s>>>(ei);
    k_repack_count <<<(NEDGES + 255) / 256, 256, 0, g_ss.s>>>(ei);
    k_scan1        <<<SCAN_NBLK, SCAN_BS, 0, g_ss.s>>>();
    k_scan2        <<<1, 128, 0, g_ss.s>>>();
    k_scan3        <<<SCAN_NBLK, SCAN_BS, 0, g_ss.s>>>();
    k_scatter      <<<(NEDGES + 255) / 256, 256, 0, g_ss.s>>>();
    cudaEventRecord(g_ss.evJoin, g_ss.s);

    k_gemm1        <<<NNODES / 32, 128>>>(x, W1);

    cudaStreamWaitEvent(0, g_ss.evJoin, 0);

    k_agg1         <<<(NNODES + 7) / 8, 256>>>(b1);
    k_gemm2        <<<NNODES / 32, 160>>>(W2);
    k_agg2         <<<(NNODES + 7) / 8, 256>>>(b2, out);
}